// round 3
// baseline (speedup 1.0000x reference)
#include <cuda_runtime.h>

#define Bv 8
#define Nv 128
#define Tv 256
#define Lv 32
#define Hv 128
#define TTv 224   // T - L

// Scratch (static device globals; allocation-free)
__device__ float g_wsum8[8 * Nv * Hv];     // partial sum_j W_fc[n,j,h] (8 j-slabs)
__device__ float g_bsum[Nv];               // sum_j b_fc[n,j]
__device__ float g_hsum[Bv * Nv * Hv];     // sum_t h[b,n,t,h]/x[b,n,t+L]
__device__ float g_R[Bv * Nv];             // sum_t 1/x[b,n,t+L]

typedef unsigned long long u64t;

__device__ __forceinline__ u64t ffma2(u64t a, u64t b, u64t c) {
    u64t d;
    asm("fma.rn.f32x2 %0, %1, %2, %3;" : "=l"(d) : "l"(a), "l"(b), "l"(c));
    return d;
}
__device__ __forceinline__ u64t pack2(float lo, float hi) {
    u64t u;
    asm("mov.b64 %0, {%1, %2};" : "=l"(u) : "f"(lo), "f"(hi));
    return u;
}
__device__ __forceinline__ float2 unpack2(u64t u) {
    float2 r;
    asm("mov.b64 {%0, %1}, %2;" : "=f"(r.x), "=f"(r.y) : "l"(u));
    return r;
}
__device__ __forceinline__ float tanh_fast(float v) {
    float r;
    asm("tanh.approx.f32 %0, %1;" : "=f"(r) : "f"(v));
    return r;
}
__device__ __forceinline__ float sig_fast(float v) {
    return fmaf(0.5f, tanh_fast(0.5f * v), 0.5f);
}

// ---------------------------------------------------------------------------
// K0: partial Wsum[n,h] over 8 j-slabs (16 j each); bsum[n]
// ---------------------------------------------------------------------------
__global__ void __launch_bounds__(128) k_prep(const float* __restrict__ Wfc,
                                              const float* __restrict__ bfc) {
    const int n = blockIdx.x, jc = blockIdx.y, h = threadIdx.x;
    const float* p = Wfc + (size_t)n * Nv * Hv + (size_t)jc * 16 * Hv + h;
    float s = 0.f;
#pragma unroll
    for (int j = 0; j < 16; j++) s += p[(size_t)j * Hv];
    g_wsum8[(jc * Nv + n) * Hv + h] = s;

    if (jc == 0) {
        float bvv = bfc[n * Nv + h];
#pragma unroll
        for (int off = 16; off; off >>= 1) bvv += __shfl_xor_sync(0xffffffffu, bvv, off);
        __shared__ float red[4];
        if ((h & 31) == 0) red[h >> 5] = bvv;
        __syncthreads();
        if (h == 0) g_bsum[n] = red[0] + red[1] + red[2] + red[3];
    }
}

// ---------------------------------------------------------------------------
// K1: gates -> h ; accumulates Hsum, R ; writes X_hat directly.
// Block (n,b), 128 threads = 64 h-pairs x 2 t-halves.
// Weights pre-packed (W[h0][l], W[h1][l]) as u64 in SMEM; x as (v,v) pairs.
// Inner: acc[t] = ffma2(xdup[t+l], Wp[g][l][hp], acc[t]).
// ---------------------------------------------------------------------------
#define SM_WP    0
#define SM_XDUP  49152
#define SM_XS    51200
#define SM_RXS   52224
#define SM_RED   53120
#define SM_HPART 53248
#define SM_TOTAL 54272

__global__ void __launch_bounds__(128) k_lstm(const float* __restrict__ x,
                                              const float* __restrict__ Wih,
                                              const float* __restrict__ bih,
                                              const float* __restrict__ bhh,
                                              float* __restrict__ outX) {
    extern __shared__ __align__(16) unsigned char smraw[];
    u64t*  Wp    = (u64t*)(smraw + SM_WP);      // [3][32][64] packed h-pairs
    u64t*  xdup  = (u64t*)(smraw + SM_XDUP);    // [256] (x[t], x[t])
    float* xs    = (float*)(smraw + SM_XS);     // [256]
    float* rxs   = (float*)(smraw + SM_RXS);    // [224]
    float* red   = (float*)(smraw + SM_RED);    // [4][8]
    u64t*  hpart = (u64t*)(smraw + SM_HPART);   // [128]

    const int n = blockIdx.x, b = blockIdx.y;
    const int tid = threadIdx.x;
    const int lane = tid & 31, warp = tid >> 5;
    const int tg = tid >> 6, hp = tid & 63;
    const int h0 = 2 * hp, h1 = h0 + 1;

    const float* xrow = x + ((size_t)b * Nv + n) * Tv;
    xs[tid] = xrow[tid];
    xs[tid + 128] = xrow[tid + 128];
    __syncthreads();

    for (int i = tid; i < Tv; i += 128) { float v = xs[i]; xdup[i] = pack2(v, v); }
    for (int i = tid; i < TTv; i += 128) rxs[i] = 1.0f / xs[i + Lv];

    // Stage weights pre-packed: word-index view, Wpf[(g*32+l)*128 + h] = W[n,grow,h,l]
    {
        float* Wpf = (float*)Wp;
        const float* Wn = Wih + (size_t)n * 4 * Hv * Lv;
        for (int idx = tid; idx < 3 * Hv; idx += 128) {
            const int g3 = idx >> 7, h = idx & 127;
            const int grow = (g3 == 0) ? 0 : (g3 + 1);   // gates i, g, o (f dead)
            const float4* src = (const float4*)(Wn + ((size_t)grow * Hv + h) * Lv);
#pragma unroll
            for (int q = 0; q < 8; q++) {
                float4 v = src[q];
                const int base = (g3 * 32 + 4 * q) * 128 + h;
                Wpf[base]       = v.x;
                Wpf[base + 128] = v.y;
                Wpf[base + 256] = v.z;
                Wpf[base + 384] = v.w;
            }
        }
    }

    // Biases (packed per h-pair) and wsum
    const size_t bb4 = (size_t)n * 4 * Hv;
    const u64t bi2 = pack2(bih[bb4 + h0] + bhh[bb4 + h0],
                           bih[bb4 + h1] + bhh[bb4 + h1]);
    const u64t bg2 = pack2(bih[bb4 + 2 * Hv + h0] + bhh[bb4 + 2 * Hv + h0],
                           bih[bb4 + 2 * Hv + h1] + bhh[bb4 + 2 * Hv + h1]);
    const u64t bo2 = pack2(bih[bb4 + 3 * Hv + h0] + bhh[bb4 + 3 * Hv + h0],
                           bih[bb4 + 3 * Hv + h1] + bhh[bb4 + 3 * Hv + h1]);
    float ws0 = 0.f, ws1 = 0.f;
#pragma unroll
    for (int s = 0; s < 8; s++) {
        ws0 += g_wsum8[(s * Nv + n) * Hv + h0];
        ws1 += g_wsum8[(s * Nv + n) * Hv + h1];
    }
    const float bsum_n = g_bsum[n];
    __syncthreads();

    // R[b,n]
    {
        float r = 0.f;
        for (int i = tid; i < TTv; i += 128) r += rxs[i];
#pragma unroll
        for (int off = 16; off; off >>= 1) r += __shfl_xor_sync(0xffffffffu, r, off);
        if (lane == 0) red[warp * 8] = r;
        __syncthreads();
        if (tid == 0) g_R[b * Nv + n] = red[0] + red[8] + red[16] + red[24];
        __syncthreads();
    }

    float hs0 = 0.f, hs1 = 0.f;

    for (int it = 0; it < TTv / 16; it++) {
        const int t0 = it * 16 + tg * 8;
        u64t ai[8], ag[8], ao[8];
#pragma unroll
        for (int tt = 0; tt < 8; tt++) { ai[tt] = bi2; ag[tt] = bg2; ao[tt] = bo2; }

        const u64t* xd = xdup + t0;
#pragma unroll 4
        for (int l = 0; l < Lv; l++) {
            const u64t wi2 = Wp[l * 64 + hp];
            const u64t wg2 = Wp[(32 + l) * 64 + hp];
            const u64t wo2 = Wp[(64 + l) * 64 + hp];
#pragma unroll
            for (int tt = 0; tt < 8; tt++) {
                const u64t xv = xd[l + tt];
                ai[tt] = ffma2(xv, wi2, ai[tt]);
                ag[tt] = ffma2(xv, wg2, ag[tt]);
                ao[tt] = ffma2(xv, wo2, ao[tt]);
            }
        }

        float sx[8];
#pragma unroll
        for (int tt = 0; tt < 8; tt++) {
            const float2 vi = unpack2(ai[tt]);
            const float2 vg = unpack2(ag[tt]);
            const float2 vo = unpack2(ao[tt]);
            const float c0  = sig_fast(vi.x) * tanh_fast(vg.x);
            const float hv0 = sig_fast(vo.x) * tanh_fast(c0);
            const float c1  = sig_fast(vi.y) * tanh_fast(vg.y);
            const float hv1 = sig_fast(vo.y) * tanh_fast(c1);
            const float rv  = rxs[t0 + tt];
            hs0 = fmaf(hv0, rv, hs0);
            hs1 = fmaf(hv1, rv, hs1);
            sx[tt] = fmaf(hv0, ws0, hv1 * ws1);
        }

        // X_hat: reduce over 64 h-pairs (2 warps per t-group)
#pragma unroll
        for (int tt = 0; tt < 8; tt++) {
            float v = sx[tt];
            v += __shfl_xor_sync(0xffffffffu, v, 16);
            v += __shfl_xor_sync(0xffffffffu, v, 8);
            v += __shfl_xor_sync(0xffffffffu, v, 4);
            v += __shfl_xor_sync(0xffffffffu, v, 2);
            v += __shfl_xor_sync(0xffffffffu, v, 1);
            if (lane == 0) red[warp * 8 + tt] = v;
        }
        __syncthreads();
        if (tid < 16) {
            const int tt = tid & 7, tgw = tid >> 3;
            const float s = red[(2 * tgw) * 8 + tt] + red[(2 * tgw + 1) * 8 + tt];
            outX[((size_t)b * TTv + it * 16 + tid) * Nv + n] = s + bsum_n + 1e-6f;
        }
        __syncthreads();
    }

    // Hsum: combine the two t-halves per h-pair
    hpart[tid] = pack2(hs0, hs1);
    __syncthreads();
    if (tg == 0) {
        const float2 p0 = unpack2(hpart[hp]);
        const float2 p1 = unpack2(hpart[64 + hp]);
        float2 o; o.x = p0.x + p1.x; o.y = p0.y + p1.y;
        ((float2*)(g_hsum + ((size_t)b * Nv + n) * Hv))[hp] = o;
    }
}

// ---------------------------------------------------------------------------
// K2: G[b,j,n] = (sum_h W_fc[n,j,h]*Hsum[b,n,h] + b_fc[n,j]*R[b,n]) / 224
// ---------------------------------------------------------------------------
__global__ void __launch_bounds__(256) k_gout(const float* __restrict__ Wfc,
                                              const float* __restrict__ bfc,
                                              float* __restrict__ outG) {
    const int n = blockIdx.x;
    const int tid = threadIdx.x;
    const int w = tid >> 5, lane = tid & 31;
    __shared__ __align__(16) float Hs[Bv][Hv];
    __shared__ float Rs[Bv];

    for (int i = tid; i < Bv * Hv; i += 256) {
        int bb = i >> 7, hh = i & 127;
        Hs[bb][hh] = g_hsum[((size_t)bb * Nv + n) * Hv + hh];
    }
    if (tid < Bv) Rs[tid] = g_R[tid * Nv + n];
    __syncthreads();

    float Hl[Bv][4];
#pragma unroll
    for (int bb = 0; bb < Bv; bb++) {
        float4 v = *(const float4*)&Hs[bb][4 * lane];
        Hl[bb][0] = v.x; Hl[bb][1] = v.y; Hl[bb][2] = v.z; Hl[bb][3] = v.w;
    }

    const float sc = 1.0f / (float)TTv;
#pragma unroll 2
    for (int jj = 0; jj < 16; jj++) {
        const int j = w * 16 + jj;
        const float4 wv = ((const float4*)(Wfc + ((size_t)n * Nv + j) * Hv))[lane];
        float acc[Bv];
#pragma unroll
        for (int bb = 0; bb < Bv; bb++) {
            acc[bb] = wv.x * Hl[bb][0] + wv.y * Hl[bb][1] +
                      wv.z * Hl[bb][2] + wv.w * Hl[bb][3];
        }
#pragma unroll
        for (int off = 16; off; off >>= 1) {
#pragma unroll
            for (int bb = 0; bb < Bv; bb++)
                acc[bb] += __shfl_xor_sync(0xffffffffu, acc[bb], off);
        }
        if (lane == 0) {
            const float bj = bfc[n * Nv + j];
#pragma unroll
            for (int bb = 0; bb < Bv; bb++)
                outG[((size_t)bb * Nv + j) * Nv + n] = (acc[bb] + bj * Rs[bb]) * sc;
        }
    }
}

// ---------------------------------------------------------------------------
extern "C" void kernel_launch(void* const* d_in, const int* in_sizes, int n_in,
                              void* d_out, int out_size) {
    (void)in_sizes; (void)n_in; (void)out_size;
    const float* x   = (const float*)d_in[0];
    const float* Wih = (const float*)d_in[1];
    const float* bih = (const float*)d_in[2];
    const float* bhh = (const float*)d_in[3];
    const float* Wfc = (const float*)d_in[4];
    const float* bfc = (const float*)d_in[5];

    float* outG = (float*)d_out;                       // (B, N, N)
    float* outX = outG + (size_t)Bv * Nv * Nv;         // (B, Ttau, N)

    cudaFuncSetAttribute(k_lstm, cudaFuncAttributeMaxDynamicSharedMemorySize, SM_TOTAL);

    dim3 g0(Nv, 8);
    k_prep<<<g0, 128>>>(Wfc, bfc);
    dim3 g1(Nv, Bv);
    k_lstm<<<g1, 128, SM_TOTAL>>>(x, Wih, bih, bhh, outX);
    k_gout<<<Nv, 256>>>(Wfc, bfc, outG);
}